// round 7
// baseline (speedup 1.0000x reference)
#include <cuda_runtime.h>
#include <math.h>

#define N_ENT   14541
#define EMB_DIM 768
#define EMB_V4  192            // EMB_DIM / 4
#define TOP_K   1000
#define NEG_T   5
#define BS      128
#define MARGIN  0.5f

#define KSLICES 4
#define KSEG    (TOP_K / KSLICES)      // 250
#define A_BLKS  (BS * KSLICES)         // 512 alpha partial blocks
#define STRIDE  29                     // one alpha block per 29 grid slots
#define GRID_SZ (A_BLKS + N_ENT)       // 15053

// Scratch (no cudaMalloc allowed)
__device__ float  g_simi_mean[N_ENT];
__device__ float4 g_psum[A_BLKS * EMB_V4];   // per (block, dim-group) partial sums
__device__ float4 g_psq [A_BLKS * EMB_V4];   // per (block, dim-group) partial sumsq
__device__ float  g_alpha[BS];
__device__ unsigned int g_done;              // zero-init; reset by last block

// ---------------------------------------------------------------------------
// Block reduce: valid result in thread 0.
// ---------------------------------------------------------------------------
__device__ __forceinline__ float block_reduce_sum(float v, float* sh) {
    #pragma unroll
    for (int o = 16; o > 0; o >>= 1) v += __shfl_down_sync(0xffffffffu, v, o);
    int wid = threadIdx.x >> 5;
    int lid = threadIdx.x & 31;
    if (lid == 0) sh[wid] = v;
    __syncthreads();
    int nw = blockDim.x >> 5;
    if (wid == 0) {
        v = (lid < nw) ? sh[lid] : 0.0f;
        #pragma unroll
        for (int o = 16; o > 0; o >>= 1) v += __shfl_down_sync(0xffffffffu, v, o);
    }
    return v;
}

// ---------------------------------------------------------------------------
// Fused kernel 1 (alpha blocks interleaved 1-per-29 through the grid so their
// L2 demand is spread evenly across the whole DRAM-stream duration):
//   alpha block (b, slice): gathers emb rows for its 250-k segment, writes raw
//       per-dim-group float4 sum/sumsq partials (no atomics, deterministic).
//   row block r: per-row mean of simi_score_mtx (__ldcs streaming so the emb
//       table stays L2-resident).
// ---------------------------------------------------------------------------
__global__ __launch_bounds__(256)
void fused_kernel(const float* __restrict__ simi,
                  const int*   __restrict__ ent_idx,
                  const float* __restrict__ emb) {
    __shared__ int   s_idx[KSEG];
    __shared__ float sh[8];
    const int tid = threadIdx.x;
    const int bid = blockIdx.x;

    const int q   = bid / STRIDE;
    const int rem = bid % STRIDE;
    const bool is_alpha = (rem == 0) && (q < A_BLKS);

    if (is_alpha) {
        // ================= alpha Phase A partial =================
        const int ab    = q;                     // alpha block id
        const int b     = ab >> 2;               // sample
        const int slice = ab & 3;                // k-slice
        const int k0    = slice * KSEG;

        for (int k = tid; k < KSEG; k += 256)
            s_idx[k] = ent_idx[b * TOP_K + k0 + k];
        __syncthreads();

        if (tid < EMB_V4) {
            // Thread tid owns dims [4*tid, 4*tid+4). A warp = 32 consecutive
            // float4s of the SAME row -> fully coalesced 512B bursts.
            const float4* __restrict__ emb4 = (const float4*)emb;
            float s0 = 0.f, s1 = 0.f, s2 = 0.f, s3 = 0.f;
            float q0 = 0.f, q1 = 0.f, q2 = 0.f, q3 = 0.f;
            #pragma unroll 5
            for (int k = 0; k < KSEG; k++) {
                float4 v = __ldg(emb4 + (size_t)s_idx[k] * EMB_V4 + tid);
                s0 += v.x; s1 += v.y; s2 += v.z; s3 += v.w;
                q0 = fmaf(v.x, v.x, q0); q1 = fmaf(v.y, v.y, q1);
                q2 = fmaf(v.z, v.z, q2); q3 = fmaf(v.w, v.w, q3);
            }
            g_psum[ab * EMB_V4 + tid] = make_float4(s0, s1, s2, s3);
            g_psq [ab * EMB_V4 + tid] = make_float4(q0, q1, q2, q3);
        }
    } else {
        // Row index: subtract the number of alpha blocks at smaller blockIdx.
        const int n_alpha_before = (rem != 0) ? min(q + 1, A_BLKS) : A_BLKS;
        const int r = bid - n_alpha_before;

        const size_t e0 = (size_t)r * N_ENT;
        const size_t e1 = e0 + N_ENT;
        const size_t a0 = (e0 + 3) & ~(size_t)3;   // first 16B-aligned element
        const size_t a1 = e1 & ~(size_t)3;

        float s = 0.0f;
        for (size_t e = e0 + tid; e < a0; e += 256) s += __ldcs(simi + e);
        for (size_t e = a1 + tid; e < e1; e += 256) s += __ldcs(simi + e);

        const float4* __restrict__ v4 = (const float4*)(simi + a0);
        const int nv = (int)((a1 - a0) >> 2);
        float4 a = make_float4(0.f, 0.f, 0.f, 0.f);
        #pragma unroll 4
        for (int i = tid; i < nv; i += 256) {
            float4 x = __ldcs(v4 + i);
            a.x += x.x; a.y += x.y; a.z += x.z; a.w += x.w;
        }
        s += (a.x + a.y) + (a.z + a.w);
        s = block_reduce_sum(s, sh);
        if (tid == 0) g_simi_mean[r] = s * (1.0f / (float)N_ENT);
    }
}

// ---------------------------------------------------------------------------
// Kernel 2: combine Phase-A partials (std * w) + Phase B + sigmoid, then the
// last block to finish computes the margin loss (fence + counter pattern;
// deterministic: loss reads g_alpha in fixed order).
// One block (256 threads) per sample.
// ---------------------------------------------------------------------------
__global__ __launch_bounds__(256)
void phaseB_loss_kernel(const int*   __restrict__ ent_idx,
                        const float* __restrict__ stelp_scores,
                        const float* __restrict__ rotate_scores,
                        const float* __restrict__ proj_w,
                        const float* __restrict__ proj_b,
                        const float* __restrict__ pos_s,
                        const float* __restrict__ pos_r,
                        const float* __restrict__ neg_s,
                        const float* __restrict__ neg_r,
                        float* __restrict__ out) {
    __shared__ float sh[8];
    __shared__ int   s_last;
    const int b   = blockIdx.x;
    const int tid = threadIdx.x;

    float acc = 0.0f;

    // ---- combine the 4 k-slice partials, compute std(ddof=1) dot w ----
    if (tid < EMB_V4) {
        float4 S = make_float4(0.f, 0.f, 0.f, 0.f);
        float4 Q = make_float4(0.f, 0.f, 0.f, 0.f);
        #pragma unroll
        for (int s = 0; s < KSLICES; s++) {
            int pb = (b << 2) + s;
            float4 ps = g_psum[pb * EMB_V4 + tid];
            float4 pq = g_psq [pb * EMB_V4 + tid];
            S.x += ps.x; S.y += ps.y; S.z += ps.z; S.w += ps.w;
            Q.x += pq.x; Q.y += pq.y; Q.z += pq.z; Q.w += pq.w;
        }
        const float invK  = 1.0f / (float)TOP_K;
        const float invK1 = 1.0f / (float)(TOP_K - 1);
        float ss[4] = {S.x, S.y, S.z, S.w};
        float qq[4] = {Q.x, Q.y, Q.z, Q.w};
        #pragma unroll
        for (int c = 0; c < 4; c++) {
            float mean = ss[c] * invK;
            float var  = fmaxf((qq[c] - ss[c] * mean) * invK1, 0.0f);
            acc = fmaf(sqrtf(var), __ldg(proj_w + 4 * tid + c), acc);
        }
    }

    // ---- Phase B: simi + score feature groups ----
    const float* wS  = proj_w + EMB_DIM;                // simi
    const float* wD  = proj_w + EMB_DIM + TOP_K;        // |rot - stelp|
    const float* wA  = proj_w + EMB_DIM + 2 * TOP_K;    // stelp + rot
    const float* wSt = proj_w + EMB_DIM + 3 * TOP_K;    // stelp
    const float* wR  = proj_w + EMB_DIM + 4 * TOP_K;    // rot

    for (int k = tid; k < TOP_K; k += 256) {
        int   ix = ent_idx[b * TOP_K + k];
        float ss = stelp_scores[b * TOP_K + k];
        float rr = rotate_scores[b * TOP_K + k];
        float sm = g_simi_mean[ix];
        acc = fmaf(wS[k],  sm,             acc);
        acc = fmaf(wD[k],  fabsf(rr - ss), acc);
        acc = fmaf(wA[k],  ss + rr,        acc);
        acc = fmaf(wSt[k], ss,             acc);
        acc = fmaf(wR[k],  rr,             acc);
    }
    float total = block_reduce_sum(acc, sh);

    // ---- publish alpha, elect last block ----
    if (tid == 0) {
        float z = total + proj_b[0];
        g_alpha[b] = 1.0f / (1.0f + __expf(-z));
        __threadfence();
        unsigned int prev = atomicAdd(&g_done, 1u);
        s_last = (prev == (unsigned int)(BS - 1)) ? 1 : 0;
    }
    __syncthreads();

    // ---- last block computes the loss ----
    if (s_last) {
        float lacc = 0.f;
        for (int i = tid; i < BS * NEG_T; i += 256) {
            int bb = i / NEG_T;
            float a  = g_alpha[bb];
            float pe = a * pos_s[bb] + (1.0f - a) * pos_r[bb];
            float ne = a * neg_s[i] + (1.0f - a) * neg_r[i];
            lacc += fmaxf(MARGIN - pe + ne, 0.0f);
        }
        float lsum = block_reduce_sum(lacc, sh);
        if (tid == 0) {
            out[0] = lsum * (1.0f / (float)(BS * NEG_T));
            g_done = 0;   // reset for next replay
        }
    }
}

// ---------------------------------------------------------------------------
extern "C" void kernel_launch(void* const* d_in, const int* in_sizes, int n_in,
                              void* d_out, int out_size) {
    const float* pos_stelp  = (const float*)d_in[0];
    const float* pos_rotate = (const float*)d_in[1];
    const int*   ent_idx    = (const int*)  d_in[2];
    const float* neg_stelp  = (const float*)d_in[3];
    const float* neg_rotate = (const float*)d_in[4];
    const float* stelp_sc   = (const float*)d_in[5];
    const float* rotate_sc  = (const float*)d_in[6];
    const float* ent_emb    = (const float*)d_in[7];
    const float* simi_mtx   = (const float*)d_in[8];
    const float* proj_w     = (const float*)d_in[9];
    const float* proj_b     = (const float*)d_in[10];
    float* out = (float*)d_out;

    fused_kernel<<<GRID_SZ, 256>>>(simi_mtx, ent_idx, ent_emb);
    phaseB_loss_kernel<<<BS, 256>>>(ent_idx, stelp_sc, rotate_sc, proj_w, proj_b,
                                    pos_stelp, pos_rotate, neg_stelp, neg_rotate,
                                    out);
}

// round 8
// speedup vs baseline: 1.1078x; 1.1078x over previous
#include <cuda_runtime.h>
#include <math.h>

#define N_ENT   14541
#define EMB_DIM 768
#define EMB_V4  192            // EMB_DIM / 4
#define TOP_K   1000
#define NEG_T   5
#define BS      128
#define MARGIN  0.5f

#define KSLICES 4
#define KSEG    (TOP_K / KSLICES)      // 250
#define A_BLKS  (BS * KSLICES)         // 512 alpha partial blocks

// Scratch (no cudaMalloc allowed)
__device__ float  g_simi_mean[N_ENT];
__device__ float4 g_psum[A_BLKS * EMB_V4];   // per (block, dim-group) partial sums
__device__ float4 g_psq [A_BLKS * EMB_V4];   // per (block, dim-group) partial sumsq

// ---------------------------------------------------------------------------
// Block reduce: valid result in thread 0.
// ---------------------------------------------------------------------------
__device__ __forceinline__ float block_reduce_sum(float v, float* sh) {
    #pragma unroll
    for (int o = 16; o > 0; o >>= 1) v += __shfl_down_sync(0xffffffffu, v, o);
    int wid = threadIdx.x >> 5;
    int lid = threadIdx.x & 31;
    if (lid == 0) sh[wid] = v;
    __syncthreads();
    int nw = blockDim.x >> 5;
    if (wid == 0) {
        v = (lid < nw) ? sh[lid] : 0.0f;
        #pragma unroll
        for (int o = 16; o > 0; o >>= 1) v += __shfl_down_sync(0xffffffffu, v, o);
    }
    return v;
}

// ---------------------------------------------------------------------------
// Fused kernel 1 (R6 schedule: alpha blocks FIRST as one short burst):
//   blocks [0, A_BLKS):          alpha Phase A partials. Block (b, slice)
//       gathers emb rows for its 250-k segment, writes raw per-dim-group
//       float4 sum/sumsq partials (no reduction, no atomics, deterministic).
//   blocks [A_BLKS, A_BLKS+N_ENT): per-row mean of simi_score_mtx
//       (DRAM-bound, __ldcs streaming so the emb table stays L2-resident).
// Block A_BLKS also zeroes out[0] for the atomic loss accumulation in k2.
// ---------------------------------------------------------------------------
__global__ __launch_bounds__(256)
void fused_kernel(const float* __restrict__ simi,
                  const int*   __restrict__ ent_idx,
                  const float* __restrict__ emb,
                  float* __restrict__ out) {
    __shared__ int   s_idx[KSEG];
    __shared__ float sh[8];
    const int tid = threadIdx.x;

    if (blockIdx.x < A_BLKS) {
        // ================= alpha Phase A partial =================
        const int b     = blockIdx.x >> 2;       // sample
        const int slice = blockIdx.x & 3;        // k-slice
        const int k0    = slice * KSEG;

        for (int k = tid; k < KSEG; k += 256)
            s_idx[k] = ent_idx[b * TOP_K + k0 + k];
        __syncthreads();

        if (tid < EMB_V4) {
            // Thread tid owns dims [4*tid, 4*tid+4). A warp = 32 consecutive
            // float4s of the SAME row -> fully coalesced 512B bursts.
            const float4* __restrict__ emb4 = (const float4*)emb;
            float s0 = 0.f, s1 = 0.f, s2 = 0.f, s3 = 0.f;
            float q0 = 0.f, q1 = 0.f, q2 = 0.f, q3 = 0.f;
            #pragma unroll 10
            for (int k = 0; k < KSEG; k++) {
                float4 v = __ldg(emb4 + (size_t)s_idx[k] * EMB_V4 + tid);
                s0 += v.x; s1 += v.y; s2 += v.z; s3 += v.w;
                q0 = fmaf(v.x, v.x, q0); q1 = fmaf(v.y, v.y, q1);
                q2 = fmaf(v.z, v.z, q2); q3 = fmaf(v.w, v.w, q3);
            }
            g_psum[blockIdx.x * EMB_V4 + tid] = make_float4(s0, s1, s2, s3);
            g_psq [blockIdx.x * EMB_V4 + tid] = make_float4(q0, q1, q2, q3);
        }
    } else {
        // ================= row mean (streaming .cs loads) =================
        const int r = blockIdx.x - A_BLKS;
        if (r == 0 && tid == 0) out[0] = 0.0f;   // init for k2's atomic loss

        const size_t e0 = (size_t)r * N_ENT;
        const size_t e1 = e0 + N_ENT;
        const size_t a0 = (e0 + 3) & ~(size_t)3;   // first 16B-aligned element
        const size_t a1 = e1 & ~(size_t)3;

        float s = 0.0f;
        for (size_t e = e0 + tid; e < a0; e += 256) s += __ldcs(simi + e);
        for (size_t e = a1 + tid; e < e1; e += 256) s += __ldcs(simi + e);

        const float4* __restrict__ v4 = (const float4*)(simi + a0);
        const int nv = (int)((a1 - a0) >> 2);
        float4 a = make_float4(0.f, 0.f, 0.f, 0.f);
        #pragma unroll 4
        for (int i = tid; i < nv; i += 256) {
            float4 x = __ldcs(v4 + i);
            a.x += x.x; a.y += x.y; a.z += x.z; a.w += x.w;
        }
        s += (a.x + a.y) + (a.z + a.w);
        s = block_reduce_sum(s, sh);
        if (tid == 0) g_simi_mean[r] = s * (1.0f / (float)N_ENT);
    }
}

// ---------------------------------------------------------------------------
// Kernel 2: combine Phase-A partials (std * w) + Phase B + sigmoid + this
// sample's margin-loss contribution (atomicAdd into out[0], zeroed by k1).
// One block (256 threads) per sample.
// ---------------------------------------------------------------------------
__global__ __launch_bounds__(256)
void phaseB_kernel(const int*   __restrict__ ent_idx,
                   const float* __restrict__ stelp_scores,
                   const float* __restrict__ rotate_scores,
                   const float* __restrict__ proj_w,
                   const float* __restrict__ proj_b,
                   const float* __restrict__ pos_s,
                   const float* __restrict__ pos_r,
                   const float* __restrict__ neg_s,
                   const float* __restrict__ neg_r,
                   float* __restrict__ out) {
    __shared__ float sh[8];
    const int b   = blockIdx.x;
    const int tid = threadIdx.x;

    float acc = 0.0f;

    // ---- combine the 4 k-slice partials, compute std(ddof=1) dot w ----
    if (tid < EMB_V4) {
        float4 S = make_float4(0.f, 0.f, 0.f, 0.f);
        float4 Q = make_float4(0.f, 0.f, 0.f, 0.f);
        #pragma unroll
        for (int s = 0; s < KSLICES; s++) {
            int pb = (b << 2) + s;
            float4 ps = g_psum[pb * EMB_V4 + tid];
            float4 pq = g_psq [pb * EMB_V4 + tid];
            S.x += ps.x; S.y += ps.y; S.z += ps.z; S.w += ps.w;
            Q.x += pq.x; Q.y += pq.y; Q.z += pq.z; Q.w += pq.w;
        }
        const float invK  = 1.0f / (float)TOP_K;
        const float invK1 = 1.0f / (float)(TOP_K - 1);
        float ss[4] = {S.x, S.y, S.z, S.w};
        float qq[4] = {Q.x, Q.y, Q.z, Q.w};
        #pragma unroll
        for (int c = 0; c < 4; c++) {
            float mean = ss[c] * invK;
            float var  = fmaxf((qq[c] - ss[c] * mean) * invK1, 0.0f);
            acc = fmaf(sqrtf(var), __ldg(proj_w + 4 * tid + c), acc);
        }
    }

    // ---- Phase B: simi + score feature groups ----
    const float* wS  = proj_w + EMB_DIM;                // simi
    const float* wD  = proj_w + EMB_DIM + TOP_K;        // |rot - stelp|
    const float* wA  = proj_w + EMB_DIM + 2 * TOP_K;    // stelp + rot
    const float* wSt = proj_w + EMB_DIM + 3 * TOP_K;    // stelp
    const float* wR  = proj_w + EMB_DIM + 4 * TOP_K;    // rot

    for (int k = tid; k < TOP_K; k += 256) {
        int   ix = ent_idx[b * TOP_K + k];
        float ss = stelp_scores[b * TOP_K + k];
        float rr = rotate_scores[b * TOP_K + k];
        float sm = g_simi_mean[ix];
        acc = fmaf(wS[k],  sm,             acc);
        acc = fmaf(wD[k],  fabsf(rr - ss), acc);
        acc = fmaf(wA[k],  ss + rr,        acc);
        acc = fmaf(wSt[k], ss,             acc);
        acc = fmaf(wR[k],  rr,             acc);
    }
    float total = block_reduce_sum(acc, sh);

    // ---- sigmoid + this sample's loss contribution ----
    if (tid == 0) {
        float z = total + proj_b[0];
        float a = 1.0f / (1.0f + __expf(-z));
        float pe = a * pos_s[b] + (1.0f - a) * pos_r[b];
        float lsum = 0.0f;
        #pragma unroll
        for (int j = 0; j < NEG_T; j++) {
            float ne = a * neg_s[b * NEG_T + j] + (1.0f - a) * neg_r[b * NEG_T + j];
            lsum += fmaxf(MARGIN - pe + ne, 0.0f);
        }
        atomicAdd(out, lsum * (1.0f / (float)(BS * NEG_T)));
    }
}

// ---------------------------------------------------------------------------
extern "C" void kernel_launch(void* const* d_in, const int* in_sizes, int n_in,
                              void* d_out, int out_size) {
    const float* pos_stelp  = (const float*)d_in[0];
    const float* pos_rotate = (const float*)d_in[1];
    const int*   ent_idx    = (const int*)  d_in[2];
    const float* neg_stelp  = (const float*)d_in[3];
    const float* neg_rotate = (const float*)d_in[4];
    const float* stelp_sc   = (const float*)d_in[5];
    const float* rotate_sc  = (const float*)d_in[6];
    const float* ent_emb    = (const float*)d_in[7];
    const float* simi_mtx   = (const float*)d_in[8];
    const float* proj_w     = (const float*)d_in[9];
    const float* proj_b     = (const float*)d_in[10];
    float* out = (float*)d_out;

    fused_kernel<<<A_BLKS + N_ENT, 256>>>(simi_mtx, ent_idx, ent_emb, out);
    phaseB_kernel<<<BS, 256>>>(ent_idx, stelp_sc, rotate_sc, proj_w, proj_b,
                               pos_stelp, pos_rotate, neg_stelp, neg_rotate,
                               out);
}

// round 9
// speedup vs baseline: 1.1229x; 1.0136x over previous
#include <cuda_runtime.h>
#include <math.h>

#define N_ENT   14541
#define EMB_DIM 768
#define EMB_V4  192            // EMB_DIM / 4
#define TOP_K   1000
#define NEG_T   5
#define BS      128
#define MARGIN  0.5f

#define KSLICES 4
#define KSEG    (TOP_K / KSLICES)      // 250
#define A_BLKS  (BS * KSLICES)         // 512 alpha partial blocks

// Scratch (no cudaMalloc allowed)
__device__ float  g_simi_mean[N_ENT];
__device__ float4 g_psum[A_BLKS * EMB_V4];   // per (block, dim-group) partial sums
__device__ float4 g_psq [A_BLKS * EMB_V4];   // per (block, dim-group) partial sumsq

// ---------------------------------------------------------------------------
// Block reduce: valid result in thread 0. Supports up to 1024 threads.
// ---------------------------------------------------------------------------
__device__ __forceinline__ float block_reduce_sum(float v, float* sh) {
    #pragma unroll
    for (int o = 16; o > 0; o >>= 1) v += __shfl_down_sync(0xffffffffu, v, o);
    int wid = threadIdx.x >> 5;
    int lid = threadIdx.x & 31;
    if (lid == 0) sh[wid] = v;
    __syncthreads();
    int nw = blockDim.x >> 5;
    if (wid == 0) {
        v = (lid < nw) ? sh[lid] : 0.0f;
        #pragma unroll
        for (int o = 16; o > 0; o >>= 1) v += __shfl_down_sync(0xffffffffu, v, o);
    }
    return v;
}

// ---------------------------------------------------------------------------
// Fused kernel 1 (alpha blocks FIRST as one short burst):
//   blocks [0, A_BLKS):          alpha Phase A partials. Block (b, slice)
//       gathers emb rows for its 250-k segment, writes raw per-dim-group
//       float4 sum/sumsq partials (no reduction, no atomics, deterministic).
//   blocks [A_BLKS, A_BLKS+N_ENT): per-row mean of simi_score_mtx
//       (DRAM-bound, __ldcs streaming so the emb table stays L2-resident).
// Block A_BLKS also zeroes out[0] for the atomic loss accumulation in k2.
// ---------------------------------------------------------------------------
__global__ __launch_bounds__(256)
void fused_kernel(const float* __restrict__ simi,
                  const int*   __restrict__ ent_idx,
                  const float* __restrict__ emb,
                  float* __restrict__ out) {
    __shared__ int   s_idx[KSEG];
    __shared__ float sh[8];
    const int tid = threadIdx.x;

    if (blockIdx.x < A_BLKS) {
        // ================= alpha Phase A partial =================
        const int b     = blockIdx.x >> 2;       // sample
        const int slice = blockIdx.x & 3;        // k-slice
        const int k0    = slice * KSEG;

        for (int k = tid; k < KSEG; k += 256)
            s_idx[k] = ent_idx[b * TOP_K + k0 + k];
        __syncthreads();

        if (tid < EMB_V4) {
            // Thread tid owns dims [4*tid, 4*tid+4). A warp = 32 consecutive
            // float4s of the SAME row -> fully coalesced 512B bursts.
            const float4* __restrict__ emb4 = (const float4*)emb;
            float s0 = 0.f, s1 = 0.f, s2 = 0.f, s3 = 0.f;
            float q0 = 0.f, q1 = 0.f, q2 = 0.f, q3 = 0.f;
            #pragma unroll 10
            for (int k = 0; k < KSEG; k++) {
                float4 v = __ldg(emb4 + (size_t)s_idx[k] * EMB_V4 + tid);
                s0 += v.x; s1 += v.y; s2 += v.z; s3 += v.w;
                q0 = fmaf(v.x, v.x, q0); q1 = fmaf(v.y, v.y, q1);
                q2 = fmaf(v.z, v.z, q2); q3 = fmaf(v.w, v.w, q3);
            }
            g_psum[blockIdx.x * EMB_V4 + tid] = make_float4(s0, s1, s2, s3);
            g_psq [blockIdx.x * EMB_V4 + tid] = make_float4(q0, q1, q2, q3);
        }
    } else {
        // ================= row mean (streaming .cs loads) =================
        const int r = blockIdx.x - A_BLKS;
        if (r == 0 && tid == 0) out[0] = 0.0f;   // init for k2's atomic loss

        const size_t e0 = (size_t)r * N_ENT;
        const size_t e1 = e0 + N_ENT;
        const size_t a0 = (e0 + 3) & ~(size_t)3;   // first 16B-aligned element
        const size_t a1 = e1 & ~(size_t)3;

        float s = 0.0f;
        for (size_t e = e0 + tid; e < a0; e += 256) s += __ldcs(simi + e);
        for (size_t e = a1 + tid; e < e1; e += 256) s += __ldcs(simi + e);

        const float4* __restrict__ v4 = (const float4*)(simi + a0);
        const int nv = (int)((a1 - a0) >> 2);
        float4 a = make_float4(0.f, 0.f, 0.f, 0.f);
        #pragma unroll 4
        for (int i = tid; i < nv; i += 256) {
            float4 x = __ldcs(v4 + i);
            a.x += x.x; a.y += x.y; a.z += x.z; a.w += x.w;
        }
        s += (a.x + a.y) + (a.z + a.w);
        s = block_reduce_sum(s, sh);
        if (tid == 0) g_simi_mean[r] = s * (1.0f / (float)N_ENT);
    }
}

// ---------------------------------------------------------------------------
// Kernel 2: combine Phase-A partials (std * w) + Phase B + sigmoid + this
// sample's margin-loss contribution (atomicAdd into out[0], zeroed by k1).
// One block of 1024 threads per sample: each thread owns exactly ONE k, so
// the idx->gather dependent chain is paid once, concurrently by all threads.
// ---------------------------------------------------------------------------
__global__ __launch_bounds__(1024)
void phaseB_kernel(const int*   __restrict__ ent_idx,
                   const float* __restrict__ stelp_scores,
                   const float* __restrict__ rotate_scores,
                   const float* __restrict__ proj_w,
                   const float* __restrict__ proj_b,
                   const float* __restrict__ pos_s,
                   const float* __restrict__ pos_r,
                   const float* __restrict__ neg_s,
                   const float* __restrict__ neg_r,
                   float* __restrict__ out) {
    __shared__ float sh[32];
    const int b   = blockIdx.x;
    const int tid = threadIdx.x;

    float acc = 0.0f;

    // ---- Phase B: one k per thread (tid < TOP_K) ----
    if (tid < TOP_K) {
        const int k = tid;
        const float* wS  = proj_w + EMB_DIM;                // simi
        const float* wD  = proj_w + EMB_DIM + TOP_K;        // |rot - stelp|
        const float* wA  = proj_w + EMB_DIM + 2 * TOP_K;    // stelp + rot
        const float* wSt = proj_w + EMB_DIM + 3 * TOP_K;    // stelp
        const float* wR  = proj_w + EMB_DIM + 4 * TOP_K;    // rot

        int   ix = ent_idx[b * TOP_K + k];
        float ss = stelp_scores[b * TOP_K + k];
        float rr = rotate_scores[b * TOP_K + k];
        float sm = g_simi_mean[ix];
        acc = fmaf(wS[k],  sm,             acc);
        acc = fmaf(wD[k],  fabsf(rr - ss), acc);
        acc = fmaf(wA[k],  ss + rr,        acc);
        acc = fmaf(wSt[k], ss,             acc);
        acc = fmaf(wR[k],  rr,             acc);
    }

    // ---- combine the 4 k-slice partials, compute std(ddof=1) dot w ----
    if (tid < EMB_V4) {
        float4 S = make_float4(0.f, 0.f, 0.f, 0.f);
        float4 Q = make_float4(0.f, 0.f, 0.f, 0.f);
        #pragma unroll
        for (int s = 0; s < KSLICES; s++) {
            int pb = (b << 2) + s;
            float4 ps = g_psum[pb * EMB_V4 + tid];
            float4 pq = g_psq [pb * EMB_V4 + tid];
            S.x += ps.x; S.y += ps.y; S.z += ps.z; S.w += ps.w;
            Q.x += pq.x; Q.y += pq.y; Q.z += pq.z; Q.w += pq.w;
        }
        const float invK  = 1.0f / (float)TOP_K;
        const float invK1 = 1.0f / (float)(TOP_K - 1);
        float ss[4] = {S.x, S.y, S.z, S.w};
        float qq[4] = {Q.x, Q.y, Q.z, Q.w};
        #pragma unroll
        for (int c = 0; c < 4; c++) {
            float mean = ss[c] * invK;
            float var  = fmaxf((qq[c] - ss[c] * mean) * invK1, 0.0f);
            acc = fmaf(sqrtf(var), __ldg(proj_w + 4 * tid + c), acc);
        }
    }

    float total = block_reduce_sum(acc, sh);

    // ---- sigmoid + this sample's loss contribution ----
    if (tid == 0) {
        float z = total + proj_b[0];
        float a = 1.0f / (1.0f + __expf(-z));
        float pe = a * pos_s[b] + (1.0f - a) * pos_r[b];
        float lsum = 0.0f;
        #pragma unroll
        for (int j = 0; j < NEG_T; j++) {
            float ne = a * neg_s[b * NEG_T + j] + (1.0f - a) * neg_r[b * NEG_T + j];
            lsum += fmaxf(MARGIN - pe + ne, 0.0f);
        }
        atomicAdd(out, lsum * (1.0f / (float)(BS * NEG_T)));
    }
}

// ---------------------------------------------------------------------------
extern "C" void kernel_launch(void* const* d_in, const int* in_sizes, int n_in,
                              void* d_out, int out_size) {
    const float* pos_stelp  = (const float*)d_in[0];
    const float* pos_rotate = (const float*)d_in[1];
    const int*   ent_idx    = (const int*)  d_in[2];
    const float* neg_stelp  = (const float*)d_in[3];
    const float* neg_rotate = (const float*)d_in[4];
    const float* stelp_sc   = (const float*)d_in[5];
    const float* rotate_sc  = (const float*)d_in[6];
    const float* ent_emb    = (const float*)d_in[7];
    const float* simi_mtx   = (const float*)d_in[8];
    const float* proj_w     = (const float*)d_in[9];
    const float* proj_b     = (const float*)d_in[10];
    float* out = (float*)d_out;

    fused_kernel<<<A_BLKS + N_ENT, 256>>>(simi_mtx, ent_idx, ent_emb, out);
    phaseB_kernel<<<BS, 1024>>>(ent_idx, stelp_sc, rotate_sc, proj_w, proj_b,
                                pos_stelp, pos_rotate, neg_stelp, neg_rotate,
                                out);
}